// round 2
// baseline (speedup 1.0000x reference)
#include <cuda_runtime.h>
#include <math.h>

typedef unsigned long long u64;

#define TM 8          // nodes per CTA
#define NT 256        // threads per CTA

// shared memory layout (float offsets)
#define S_A1 0                      // vec tile   [24][260]
#define S_V2 (S_A1 + 24*260)        // vec2       [24][260]
#define S_A2 (S_V2 + 24*260)        // hcat       [8][516]  (x | scalar)
#define S_H  (S_A2 + 8*516)         // h          [8][258]
#define S_VD (S_H  + 8*258)         // vec_dot    [8][256]
#define S_TOT (S_VD + 8*256)        // = 20720 floats = 82880 bytes

__device__ __forceinline__ void fma2(u64 &d, u64 a, u64 b) {
    asm("fma.rn.f32x2 %0, %1, %2, %0;" : "+l"(d) : "l"(a), "l"(b));
}
__device__ __forceinline__ u64 pck(float x, float y) {
    u64 r; asm("mov.b64 %0, {%1,%2};" : "=l"(r) : "f"(x), "f"(y)); return r;
}
__device__ __forceinline__ float fold(u64 v) {
    float x, y; asm("mov.b64 {%0,%1}, %2;" : "=f"(x), "=f"(y) : "l"(v));
    return x + y;
}

__global__ void __launch_bounds__(NT)
fte_kernel(const float* __restrict__ gx,
           const float* __restrict__ gvec,
           const float* __restrict__ gWe,   // [256][512]
           const float* __restrict__ gW1,   // [512][256]
           const float* __restrict__ gb1,   // [256]
           const float* __restrict__ gW2,   // [256][768]
           const float* __restrict__ gb2,   // [768]
           float* __restrict__ gout,
           int n)
{
    extern __shared__ float sm[];
    const int tid = threadIdx.x;
    const int n0  = blockIdx.x * TM;
    const int nv  = (n - n0 < TM) ? (n - n0) : TM;   // valid nodes (always 8 here)
    const int R   = 3 * nv;

    // ---- prologue: stage vec -> A1[row][260], row = local_node*3 + c ----
    {
        const float4* vsrc = (const float4*)(gvec + (size_t)n0 * 768);
        for (int i = tid; i < R * 64; i += NT) {
            float4 v = vsrc[i];
            int r = i >> 6, h4 = (i & 63) << 2;
            *(float4*)&sm[S_A1 + r * 260 + h4] = v;
        }
        if (nv < TM) {  // zero-fill unused rows (never taken for N=100000)
            for (int i = tid + R * 64; i < 24 * 64; i += NT) {
                int r = i >> 6, h4 = (i & 63) << 2;
                *(float4*)&sm[S_A1 + r * 260 + h4] = make_float4(0.f, 0.f, 0.f, 0.f);
            }
        }
    }
    __syncthreads();

    const int j = tid;  // this thread's output column, 0..255

    // ---- phase 1: v[24][512] = A1 @ W_equi ; thread owns cols j (vec1), j+256 (vec2) ----
    {
        u64 a1[24], a2[24];
        #pragma unroll
        for (int r = 0; r < 24; r++) { a1[r] = 0ull; a2[r] = 0ull; }

        #pragma unroll 2
        for (int kk = 0; kk < 128; kk++) {
            const int k = kk * 2;
            const float* W = gWe + (size_t)k * 512;
            u64 b1 = pck(W[j],        W[512 + j]);
            u64 b2 = pck(W[256 + j],  W[768 + j]);
            #pragma unroll
            for (int r = 0; r < 24; r++) {
                u64 a = *(const u64*)&sm[S_A1 + r * 260 + k];
                fma2(a1[r], a, b1);
                fma2(a2[r], a, b2);
            }
        }
        // epilogue: scalar (norm), vec_dot, stash vec2
        #pragma unroll
        for (int nd = 0; nd < TM; nd++) {
            float v1a = fold(a1[3*nd]), v1b = fold(a1[3*nd+1]), v1c = fold(a1[3*nd+2]);
            float v2a = fold(a2[3*nd]), v2b = fold(a2[3*nd+1]), v2c = fold(a2[3*nd+2]);
            sm[S_A2 + nd*516 + 256 + j] = sqrtf(v1a*v1a + v1b*v1b + v1c*v1c);
            sm[S_VD + nd*256 + j] = (v1a*v2a + v1b*v2b + v1c*v2c) * 0.0625f;  // 1/sqrt(256)
            sm[S_V2 + (3*nd  )*260 + j] = v2a;
            sm[S_V2 + (3*nd+1)*260 + j] = v2b;
            sm[S_V2 + (3*nd+2)*260 + j] = v2c;
        }
    }
    // stage x -> A2[:, 0:256]
    {
        const float4* xsrc = (const float4*)(gx + (size_t)n0 * 256);
        for (int i = tid; i < nv * 64; i += NT) {
            float4 v = xsrc[i];
            int nd = i >> 6, h4 = (i & 63) << 2;
            *(float4*)&sm[S_A2 + nd * 516 + h4] = v;
        }
    }
    __syncthreads();

    // ---- phase 2: h = silu(A2 @ W1 + b1) ; thread owns col j ----
    {
        u64 acc[TM];
        #pragma unroll
        for (int m = 0; m < TM; m++) acc[m] = 0ull;

        #pragma unroll 2
        for (int kk = 0; kk < 256; kk++) {
            const int k = kk * 2;
            const float* W = gW1 + (size_t)k * 256;
            u64 b = pck(W[j], W[256 + j]);
            #pragma unroll
            for (int m = 0; m < TM; m++) {
                u64 a = *(const u64*)&sm[S_A2 + m * 516 + k];
                fma2(acc[m], a, b);
            }
        }
        const float bb = gb1[j];
        #pragma unroll
        for (int m = 0; m < TM; m++) {
            float z = fold(acc[m]) + bb;
            sm[S_H + m * 258 + j] = z / (1.0f + __expf(-z));   // silu
        }
    }
    __syncthreads();

    // ---- phase 3: xvh = h @ W2 + b2 ; thread owns cols j, j+256, j+512 ----
    {
        u64 a1[TM], a2[TM], a3[TM];
        #pragma unroll
        for (int m = 0; m < TM; m++) { a1[m] = 0ull; a2[m] = 0ull; a3[m] = 0ull; }

        #pragma unroll 2
        for (int kk = 0; kk < 128; kk++) {
            const int k = kk * 2;
            const float* W = gW2 + (size_t)k * 768;
            u64 b1 = pck(W[j],        W[768 + j]);
            u64 b2 = pck(W[256 + j],  W[768 + 256 + j]);
            u64 b3 = pck(W[512 + j],  W[768 + 512 + j]);
            #pragma unroll
            for (int m = 0; m < TM; m++) {
                u64 a = *(const u64*)&sm[S_H + m * 258 + k];
                fma2(a1[m], a, b1);
                fma2(a2[m], a, b2);
                fma2(a3[m], a, b3);
            }
        }
        const float c1 = gb2[j], c2 = gb2[256 + j], c3 = gb2[512 + j];
        const float is2 = 0.70710678118654752440f;
        float* dxout = gout;                      // dx  [N][256]
        float* dvout = gout + (size_t)n * 256;    // dvec[N][3][256]
        #pragma unroll
        for (int m = 0; m < TM; m++) {
            if (m < nv) {
                float x1 = fold(a1[m]) + c1;
                float x2 = fold(a2[m]) + c2;
                float x3 = fold(a3[m]) + c3;
                dxout[(size_t)(n0 + m) * 256 + j] =
                    (x1 + x2 + sm[S_VD + m * 256 + j]) * is2;
                size_t base = (size_t)(n0 + m) * 768;
                dvout[base +       j] = x3 * sm[S_V2 + (3*m  ) * 260 + j];
                dvout[base + 256 + j] = x3 * sm[S_V2 + (3*m+1) * 260 + j];
                dvout[base + 512 + j] = x3 * sm[S_V2 + (3*m+2) * 260 + j];
            }
        }
    }
}

extern "C" void kernel_launch(void* const* d_in, const int* in_sizes, int n_in,
                              void* d_out, int out_size)
{
    const float* x    = (const float*)d_in[0];
    const float* vec  = (const float*)d_in[1];
    // d_in[2] = node_frame (unused)
    const float* We   = (const float*)d_in[3];
    const float* W1   = (const float*)d_in[4];
    const float* b1   = (const float*)d_in[5];
    const float* W2   = (const float*)d_in[6];
    const float* b2   = (const float*)d_in[7];
    float* out = (float*)d_out;

    const int n = in_sizes[0] / 256;
    const int smem_bytes = S_TOT * sizeof(float);   // 82880

    cudaFuncSetAttribute(fte_kernel,
                         cudaFuncAttributeMaxDynamicSharedMemorySize, smem_bytes);

    const int grid = (n + TM - 1) / TM;
    fte_kernel<<<grid, NT, smem_bytes>>>(x, vec, We, W1, b1, W2, b2, out, n);
}

// round 4
// speedup vs baseline: 1.4424x; 1.4424x over previous
#include <cuda_runtime.h>
#include <math.h>

typedef unsigned long long u64;

#define TM 8          // nodes per CTA
#define NT 256        // threads per CTA

// shared memory layout (float offsets)
#define S_A1 0                      // vec tile   [24][260]
#define S_V2 (S_A1 + 24*260)        // vec2       [24][260]
#define S_A2 (S_V2 + 24*260)        // hcat       [8][516]  (x | scalar)
#define S_H  (S_A2 + 8*516)         // h          [8][258]
#define S_VD (S_H  + 8*258)         // vec_dot    [8][256]
#define S_TOT (S_VD + 8*256)        // = 20720 floats = 82880 bytes

__device__ __forceinline__ void fma2(u64 &d, u64 a, u64 b) {
    asm("fma.rn.f32x2 %0, %1, %2, %0;" : "+l"(d) : "l"(a), "l"(b));
}
__device__ __forceinline__ u64 pck(float x, float y) {
    u64 r; asm("mov.b64 %0, {%1,%2};" : "=l"(r) : "f"(x), "f"(y)); return r;
}
__device__ __forceinline__ float fold(u64 v) {
    float x, y; asm("mov.b64 {%0,%1}, %2;" : "=f"(x), "=f"(y) : "l"(v));
    return x + y;
}

__global__ void __launch_bounds__(NT)
fte_kernel(const float* __restrict__ gx,
           const float* __restrict__ gvec,
           const float* __restrict__ gWe,   // [256][512]
           const float* __restrict__ gW1,   // [512][256]
           const float* __restrict__ gb1,   // [256]
           const float* __restrict__ gW2,   // [256][768]
           const float* __restrict__ gb2,   // [768]
           float* __restrict__ gout,
           int n)
{
    extern __shared__ float sm[];
    const int tid = threadIdx.x;
    const int n0  = blockIdx.x * TM;
    const int nv  = (n - n0 < TM) ? (n - n0) : TM;   // valid nodes (always 8 here)
    const int R   = 3 * nv;

    // ---- prologue: stage vec -> A1[row][260], row = local_node*3 + c ----
    {
        const float4* vsrc = (const float4*)(gvec + (size_t)n0 * 768);
        for (int i = tid; i < R * 64; i += NT) {
            float4 v = vsrc[i];
            int r = i >> 6, h4 = (i & 63) << 2;
            *(float4*)&sm[S_A1 + r * 260 + h4] = v;
        }
        if (nv < TM) {  // zero-fill unused rows (never taken for N=100000)
            for (int i = tid + R * 64; i < 24 * 64; i += NT) {
                int r = i >> 6, h4 = (i & 63) << 2;
                *(float4*)&sm[S_A1 + r * 260 + h4] = make_float4(0.f, 0.f, 0.f, 0.f);
            }
        }
    }
    __syncthreads();

    const int j = tid;  // this thread's output column, 0..255

    // ---- phase 1: v[24][512] = A1 @ W_equi ; thread owns cols j (vec1), j+256 (vec2) ----
    {
        u64 a1[24], a2[24];
        #pragma unroll
        for (int r = 0; r < 24; r++) { a1[r] = 0ull; a2[r] = 0ull; }

        #pragma unroll 2
        for (int kk = 0; kk < 128; kk++) {
            const int k = kk * 2;
            const float* W = gWe + (size_t)k * 512;
            u64 b1 = pck(W[j],        W[512 + j]);
            u64 b2 = pck(W[256 + j],  W[768 + j]);
            #pragma unroll
            for (int r = 0; r < 24; r++) {
                u64 a = *(const u64*)&sm[S_A1 + r * 260 + k];
                fma2(a1[r], a, b1);
                fma2(a2[r], a, b2);
            }
        }
        // epilogue: scalar (norm), vec_dot, stash vec2
        #pragma unroll
        for (int nd = 0; nd < TM; nd++) {
            float v1a = fold(a1[3*nd]), v1b = fold(a1[3*nd+1]), v1c = fold(a1[3*nd+2]);
            float v2a = fold(a2[3*nd]), v2b = fold(a2[3*nd+1]), v2c = fold(a2[3*nd+2]);
            sm[S_A2 + nd*516 + 256 + j] = sqrtf(v1a*v1a + v1b*v1b + v1c*v1c);
            sm[S_VD + nd*256 + j] = (v1a*v2a + v1b*v2b + v1c*v2c) * 0.0625f;  // 1/sqrt(256)
            sm[S_V2 + (3*nd  )*260 + j] = v2a;
            sm[S_V2 + (3*nd+1)*260 + j] = v2b;
            sm[S_V2 + (3*nd+2)*260 + j] = v2c;
        }
    }
    // stage x -> A2[:, 0:256]
    {
        const float4* xsrc = (const float4*)(gx + (size_t)n0 * 256);
        for (int i = tid; i < nv * 64; i += NT) {
            float4 v = xsrc[i];
            int nd = i >> 6, h4 = (i & 63) << 2;
            *(float4*)&sm[S_A2 + nd * 516 + h4] = v;
        }
    }
    __syncthreads();

    // ---- phase 2: h = silu(A2 @ W1 + b1) ; thread owns col j ----
    {
        u64 acc[TM];
        #pragma unroll
        for (int m = 0; m < TM; m++) acc[m] = 0ull;

        #pragma unroll 2
        for (int kk = 0; kk < 256; kk++) {
            const int k = kk * 2;
            const float* W = gW1 + (size_t)k * 256;
            u64 b = pck(W[j], W[256 + j]);
            #pragma unroll
            for (int m = 0; m < TM; m++) {
                u64 a = *(const u64*)&sm[S_A2 + m * 516 + k];
                fma2(acc[m], a, b);
            }
        }
        const float bb = gb1[j];
        #pragma unroll
        for (int m = 0; m < TM; m++) {
            float z = fold(acc[m]) + bb;
            sm[S_H + m * 258 + j] = z / (1.0f + __expf(-z));   // silu
        }
    }
    __syncthreads();

    // ---- phase 3: xvh = h @ W2 + b2 ; thread owns cols j, j+256, j+512 ----
    {
        u64 a1[TM], a2[TM], a3[TM];
        #pragma unroll
        for (int m = 0; m < TM; m++) { a1[m] = 0ull; a2[m] = 0ull; a3[m] = 0ull; }

        #pragma unroll 2
        for (int kk = 0; kk < 128; kk++) {
            const int k = kk * 2;
            const float* W = gW2 + (size_t)k * 768;
            u64 b1 = pck(W[j],        W[768 + j]);
            u64 b2 = pck(W[256 + j],  W[768 + 256 + j]);
            u64 b3 = pck(W[512 + j],  W[768 + 512 + j]);
            #pragma unroll
            for (int m = 0; m < TM; m++) {
                u64 a = *(const u64*)&sm[S_H + m * 258 + k];
                fma2(a1[m], a, b1);
                fma2(a2[m], a, b2);
                fma2(a3[m], a, b3);
            }
        }
        const float c1 = gb2[j], c2 = gb2[256 + j], c3 = gb2[512 + j];
        const float is2 = 0.70710678118654752440f;
        float* dxout = gout;                      // dx  [N][256]
        float* dvout = gout + (size_t)n * 256;    // dvec[N][3][256]
        #pragma unroll
        for (int m = 0; m < TM; m++) {
            if (m < nv) {
                float x1 = fold(a1[m]) + c1;
                float x2 = fold(a2[m]) + c2;
                float x3 = fold(a3[m]) + c3;
                dxout[(size_t)(n0 + m) * 256 + j] =
                    (x1 + x2 + sm[S_VD + m * 256 + j]) * is2;
                size_t base = (size_t)(n0 + m) * 768;
                dvout[base +       j] = x3 * sm[S_V2 + (3*m  ) * 260 + j];
                dvout[base + 256 + j] = x3 * sm[S_V2 + (3*m+1) * 260 + j];
                dvout[base + 512 + j] = x3 * sm[S_V2 + (3*m+2) * 260 + j];
            }
        }
    }
}

extern "C" void kernel_launch(void* const* d_in, const int* in_sizes, int n_in,
                              void* d_out, int out_size)
{
    const float* x    = (const float*)d_in[0];
    const float* vec  = (const float*)d_in[1];
    // d_in[2] = node_frame (unused)
    const float* We   = (const float*)d_in[3];
    const float* W1   = (const float*)d_in[4];
    const float* b1   = (const float*)d_in[5];
    const float* W2   = (const float*)d_in[6];
    const float* b2   = (const float*)d_in[7];
    float* out = (float*)d_out;

    const int n = in_sizes[0] / 256;
    const int smem_bytes = S_TOT * sizeof(float);   // 82880

    cudaFuncSetAttribute(fte_kernel,
                         cudaFuncAttributeMaxDynamicSharedMemorySize, smem_bytes);

    const int grid = (n + TM - 1) / TM;
    fte_kernel<<<grid, NT, smem_bytes>>>(x, vec, We, W1, b1, W2, b2, out, n);
}

// round 7
// speedup vs baseline: 4.4491x; 3.0846x over previous
#include <cuda_runtime.h>
#include <cuda_bf16.h>
#include <math.h>

typedef unsigned int u32; typedef unsigned long long u64;

#define MAXN 100096
__device__ float g_v  [(size_t)MAXN*3*512];
__device__ float g_hc [(size_t)MAXN*512];
__device__ float g_h  [(size_t)MAXN*256];
__device__ float g_xv [(size_t)MAXN*768];
__device__ float g_dot[(size_t)MAXN*256];

#define RS 20            // smem row stride in 4B words (bank-permuting)
#define AH 0             // A hi  [128][RS]
#define AL 2560          // A lo
#define BH 5120          // B hi  [128 n][RS]
#define BL 7680          // B lo
#define SMW 10240        // total words (40KB)

__device__ __forceinline__ void splt(float f0, float f1, u32 &hi, u32 &lo){
  __nv_bfloat162 h = __floats2bfloat162_rn(f0, f1);
  __nv_bfloat162 l = __floats2bfloat162_rn(f0 - __bfloat162float(h.x),
                                           f1 - __bfloat162float(h.y));
  hi = *(u32*)&h; lo = *(u32*)&l;
}
__device__ __forceinline__ void mma16816(float* d, u32 a0,u32 a1,u32 a2,u32 a3,
                                         u32 b0,u32 b1){
  asm volatile("mma.sync.aligned.m16n8k16.row.col.f32.bf16.bf16.f32 "
    "{%0,%1,%2,%3},{%4,%5,%6,%7},{%8,%9},{%0,%1,%2,%3};"
    : "+f"(d[0]),"+f"(d[1]),"+f"(d[2]),"+f"(d[3])
    : "r"(a0),"r"(a1),"r"(a2),"r"(a3),"r"(b0),"r"(b1));
}

__global__ void __launch_bounds__(256, 2)
gemm_k(const float* __restrict__ A, const float* __restrict__ B,
       const float* __restrict__ bias, float* __restrict__ C,
       int M, int K, int N, int mode)
{
  __shared__ u32 sm[SMW];
  const int tid  = threadIdx.x;
  const int lane = tid & 31, wid = tid >> 5;
  const int wm = (wid & 1) * 64, wn = (wid >> 1) * 32;
  const int m0 = blockIdx.y * 128, n0 = blockIdx.x * 128;
  const int g  = lane >> 2, qq = lane & 3;

  float acc[4][4][4];
  #pragma unroll
  for (int a=0;a<4;a++) for (int b=0;b<4;b++) for (int c=0;c<4;c++) acc[a][b][c]=0.f;

  for (int kc = 0; kc < K; kc += 32){
    __syncthreads();
    // ---- stage A [128 x 32] fp32 -> bf16 hi/lo ----
    #pragma unroll
    for (int q = 0; q < 4; q++){
      int idx = tid + q*256;               // 1024 float4
      int r = idx >> 3, c4 = (idx & 7) << 2;
      int gr = m0 + r; if (gr >= M) gr = M - 1;
      float4 v = *(const float4*)(A + (size_t)gr*K + kc + c4);
      u32 h0,l0,h1,l1;
      splt(v.x, v.y, h0, l0); splt(v.z, v.w, h1, l1);
      int w = r*RS + (c4 >> 1);
      *(uint2*)&sm[AH + w] = make_uint2(h0, h1);
      *(uint2*)&sm[AL + w] = make_uint2(l0, l1);
    }
    // ---- stage B [32 k x 128 n] from W[k][n] -> Bs[n][k] hi/lo ----
    #pragma unroll
    for (int q = 0; q < 8; q++){
      int idx = tid + q*256;               // 2048 (n, k-pair)
      int nl = idx & 127, kp = idx >> 7;   // kp 0..15
      const float* bp = B + (size_t)(kc + 2*kp)*N + n0 + nl;
      float f0 = bp[0], f1 = bp[N];
      u32 h,l; splt(f0, f1, h, l);
      sm[BH + nl*RS + kp] = h;
      sm[BL + nl*RS + kp] = l;
    }
    __syncthreads();
    // ---- 2 x k16 of mma ----
    #pragma unroll
    for (int k16 = 0; k16 < 2; k16++){
      const int kw = k16*8 + qq;
      u32 bh[4][2], bl[4][2];
      #pragma unroll
      for (int fn = 0; fn < 4; fn++){
        int nb = (wn + fn*8 + g)*RS + kw;
        bh[fn][0] = sm[BH + nb]; bh[fn][1] = sm[BH + nb + 4];
        bl[fn][0] = sm[BL + nb]; bl[fn][1] = sm[BL + nb + 4];
      }
      #pragma unroll
      for (int fm = 0; fm < 4; fm++){
        int rb  = (wm + fm*16 + g)*RS + kw;
        int rb8 = rb + 8*RS;
        u32 ah0 = sm[AH+rb],   ah1 = sm[AH+rb8];
        u32 ah2 = sm[AH+rb+4], ah3 = sm[AH+rb8+4];
        u32 al0 = sm[AL+rb],   al1 = sm[AL+rb8];
        u32 al2 = sm[AL+rb+4], al3 = sm[AL+rb8+4];
        #pragma unroll
        for (int fn = 0; fn < 4; fn++){
          mma16816(acc[fm][fn], ah0,ah1,ah2,ah3, bh[fn][0],bh[fn][1]);
          mma16816(acc[fm][fn], al0,al1,al2,al3, bh[fn][0],bh[fn][1]);
          mma16816(acc[fm][fn], ah0,ah1,ah2,ah3, bl[fn][0],bl[fn][1]);
        }
      }
    }
  }
  // ---- epilogue ----
  #pragma unroll
  for (int fm = 0; fm < 4; fm++){
    #pragma unroll
    for (int fn = 0; fn < 4; fn++){
      int col = n0 + wn + fn*8 + 2*qq;
      float2 bb = make_float2(0.f, 0.f);
      if (mode) bb = *(const float2*)(bias + col);
      #pragma unroll
      for (int half = 0; half < 2; half++){
        int row = m0 + wm + fm*16 + g + half*8;
        if (row < M){
          float v0 = acc[fm][fn][half*2]   + bb.x;
          float v1 = acc[fm][fn][half*2+1] + bb.y;
          if (mode == 1){
            v0 = v0 / (1.f + __expf(-v0));
            v1 = v1 / (1.f + __expf(-v1));
          }
          *(float2*)&C[(size_t)row*N + col] = make_float2(v0, v1);
        }
      }
    }
  }
}

__global__ void glue1(const float* __restrict__ x, int n){
  int nd = blockIdx.x, j = threadIdx.x;
  const float* vr = g_v + (size_t)nd*1536;
  float a0=vr[j], a1=vr[512+j], a2=vr[1024+j];
  float b0=vr[256+j], b1=vr[768+j], b2=vr[1280+j];
  g_hc[(size_t)nd*512 + j]       = x[(size_t)nd*256+j];
  g_hc[(size_t)nd*512 + 256 + j] = sqrtf(a0*a0+a1*a1+a2*a2);
  g_dot[(size_t)nd*256+j] = (a0*b0+a1*b1+a2*b2)*0.0625f;
}
__global__ void glue2(float* __restrict__ out, int n){
  int nd = blockIdx.x, j = threadIdx.x;
  const float* xv = g_xv + (size_t)nd*768;
  float x1 = xv[j], x2 = xv[256+j], x3 = xv[512+j];
  out[(size_t)nd*256+j] = (x1+x2+g_dot[(size_t)nd*256+j])*0.70710678118654752f;
  const float* vr = g_v + (size_t)nd*1536 + 256;
  float* dv = out + (size_t)n*256 + (size_t)nd*768;
  dv[j]     = x3*vr[j];
  dv[256+j] = x3*vr[512+j];
  dv[512+j] = x3*vr[1024+j];
}

extern "C" void kernel_launch(void* const* d_in, const int* in_sizes, int n_in,
                              void* d_out, int out_size)
{
  const float* x   = (const float*)d_in[0];
  const float* vec = (const float*)d_in[1];
  const float* We  = (const float*)d_in[3];
  const float* W1  = (const float*)d_in[4];
  const float* b1  = (const float*)d_in[5];
  const float* W2  = (const float*)d_in[6];
  const float* b2  = (const float*)d_in[7];
  float* out = (float*)d_out;
  const int n = in_sizes[0] / 256;

  float *pv, *phc, *ph, *pxv;
  cudaGetSymbolAddress((void**)&pv,  g_v);
  cudaGetSymbolAddress((void**)&phc, g_hc);
  cudaGetSymbolAddress((void**)&ph,  g_h);
  cudaGetSymbolAddress((void**)&pxv, g_xv);

  const int M1 = 3*n;
  gemm_k<<<dim3(4, (M1+127)/128), 256>>>(vec, We, (const float*)0, pv, M1, 256, 512, 0);
  glue1<<<n, 256>>>(x, n);
  gemm_k<<<dim3(2, (n+127)/128), 256>>>(phc, W1, b1, ph, n, 512, 256, 1);
  gemm_k<<<dim3(6, (n+127)/128), 256>>>(ph, W2, b2, pxv, n, 256, 768, 2);
  glue2<<<n, 256>>>(out, n);
}

// round 8
// speedup vs baseline: 5.8437x; 1.3135x over previous
#include <cuda_runtime.h>
#include <cuda_bf16.h>
#include <math.h>

typedef unsigned int u32; typedef unsigned long long u64;
typedef __nv_bfloat16 bf16;

#define MAXN 100096
#define MAXM (3*MAXN)
// fp32 intermediates
__device__ float g_v  [(size_t)MAXN*1536];
__device__ float g_xv [(size_t)MAXN*768];
__device__ float g_dot[(size_t)MAXN*256];
// bf16 hi/lo activations
__device__ bf16 g_vh [(size_t)MAXM*256];
__device__ bf16 g_vl [(size_t)MAXM*256];
__device__ bf16 g_hch[(size_t)MAXN*512];
__device__ bf16 g_hcl[(size_t)MAXN*512];
__device__ bf16 g_hh [(size_t)MAXN*256];
__device__ bf16 g_hl [(size_t)MAXN*256];
// bf16 hi/lo transposed weights [N][K]
__device__ bf16 g_Weh[512*256], g_Wel[512*256];
__device__ bf16 g_W1h[256*512], g_W1l[256*512];
__device__ bf16 g_W2h[768*256], g_W2l[768*256];

#define RS 20                       // smem row stride (words), bank-permuting
#define ASTRIDE 2560                // words per array (128 rows * RS)
#define SMEM_BYTES (8*ASTRIDE*4)    // 2 stages * 4 arrays = 80KB

__device__ __forceinline__ void splt(float f0, float f1, u32 &hi, u32 &lo){
  __nv_bfloat162 h = __floats2bfloat162_rn(f0, f1);
  __nv_bfloat162 l = __floats2bfloat162_rn(f0 - __bfloat162float(h.x),
                                           f1 - __bfloat162float(h.y));
  hi = *(u32*)&h; lo = *(u32*)&l;
}
__device__ __forceinline__ void mma16816(float* d, u32 a0,u32 a1,u32 a2,u32 a3,
                                         u32 b0,u32 b1){
  asm volatile("mma.sync.aligned.m16n8k16.row.col.f32.bf16.bf16.f32 "
    "{%0,%1,%2,%3},{%4,%5,%6,%7},{%8,%9},{%0,%1,%2,%3};"
    : "+f"(d[0]),"+f"(d[1]),"+f"(d[2]),"+f"(d[3])
    : "r"(a0),"r"(a1),"r"(a2),"r"(a3),"r"(b0),"r"(b1));
}
__device__ __forceinline__ u32 s2u(const void* p){ u32 a;
  asm("{.reg .u64 t; cvta.to.shared.u64 t,%1; cvt.u32.u64 %0,t;}":"=r"(a):"l"(p)); return a; }
__device__ __forceinline__ void cpa16(u32 dst, const void* src){
  asm volatile("cp.async.cg.shared.global [%0], [%1], 16;" :: "r"(dst), "l"(src));
}

__global__ void __launch_bounds__(128, 2)
gemm_k(const bf16* __restrict__ Ah, const bf16* __restrict__ Al,
       const bf16* __restrict__ Bh, const bf16* __restrict__ Bl,
       const float* __restrict__ bias,
       float* __restrict__ C, bf16* __restrict__ Ch, bf16* __restrict__ Cl,
       int M, int K, int N, int mode)
{
  extern __shared__ u32 sm[];
  const u32 sbase = s2u(sm);
  const int tid = threadIdx.x, lane = tid & 31, wid = tid >> 5;
  const int wm = (wid & 1) * 64, wn = (wid >> 1) * 64;
  const int m0 = blockIdx.y * 128, n0 = blockIdx.x * 128;
  const int g = lane >> 2, qq = lane & 3;
  const int NK = K >> 5;

  float acc[4][8][4];
  #pragma unroll
  for (int a=0;a<4;a++) for (int b=0;b<8;b++) for (int c=0;c<4;c++) acc[a][b][c]=0.f;

  const int srow = tid >> 2, sc = tid & 3;          // staging row/chunk pieces

  // ---- stage helper (macro-ish lambda): copy one 32-k slab for stage s ----
  auto stage = [&](int s, int kc){
    #pragma unroll
    for (int q = 0; q < 16; q++){
      const int a   = q >> 2;
      const int row = (q & 3) * 32 + srow;
      const u32 dst = sbase + ((s*4 + a)*ASTRIDE + row*RS + sc*4) * 4;
      const bf16* src;
      if (a < 2){
        int gr = m0 + row; if (gr >= M) gr = M - 1;
        src = (a == 0 ? Ah : Al) + (size_t)gr * K + kc + sc*8;
      } else {
        int gn = n0 + row;
        src = (a == 2 ? Bh : Bl) + (size_t)gn * K + kc + sc*8;
      }
      cpa16(dst, src);
    }
    asm volatile("cp.async.commit_group;" ::: "memory");
  };

  stage(0, 0);
  for (int it = 0; it < NK; it++){
    if (it + 1 < NK){
      stage((it + 1) & 1, (it + 1) << 5);
      asm volatile("cp.async.wait_group 1;" ::: "memory");
    } else {
      asm volatile("cp.async.wait_group 0;" ::: "memory");
    }
    __syncthreads();

    const u32* SAh = sm + ((it & 1)*4    )*ASTRIDE;
    const u32* SAl = SAh + ASTRIDE;
    const u32* SBh = SAl + ASTRIDE;
    const u32* SBl = SBh + ASTRIDE;

    #pragma unroll
    for (int k16 = 0; k16 < 2; k16++){
      const int kw = k16*8 + qq;
      u32 ah[4][4], al[4][4];
      #pragma unroll
      for (int fm = 0; fm < 4; fm++){
        int rb = (wm + fm*16 + g)*RS + kw, rb8 = rb + 8*RS;
        ah[fm][0]=SAh[rb]; ah[fm][1]=SAh[rb8]; ah[fm][2]=SAh[rb+4]; ah[fm][3]=SAh[rb8+4];
        al[fm][0]=SAl[rb]; al[fm][1]=SAl[rb8]; al[fm][2]=SAl[rb+4]; al[fm][3]=SAl[rb8+4];
      }
      #pragma unroll
      for (int fn = 0; fn < 8; fn++){
        int nb = (wn + fn*8 + g)*RS + kw;
        u32 bh0 = SBh[nb], bh1 = SBh[nb+4];
        u32 bl0 = SBl[nb], bl1 = SBl[nb+4];
        #pragma unroll
        for (int fm = 0; fm < 4; fm++){
          mma16816(acc[fm][fn], ah[fm][0],ah[fm][1],ah[fm][2],ah[fm][3], bh0,bh1);
          mma16816(acc[fm][fn], al[fm][0],al[fm][1],al[fm][2],al[fm][3], bh0,bh1);
          mma16816(acc[fm][fn], ah[fm][0],ah[fm][1],ah[fm][2],ah[fm][3], bl0,bl1);
        }
      }
    }
    __syncthreads();
  }

  // ---- epilogue ----
  #pragma unroll
  for (int fm = 0; fm < 4; fm++){
    #pragma unroll
    for (int half = 0; half < 2; half++){
      const int row = m0 + wm + fm*16 + g + half*8;
      if (row >= M) continue;
      #pragma unroll
      for (int fn = 0; fn < 8; fn++){
        const int col = n0 + wn + fn*8 + 2*qq;
        float v0 = acc[fm][fn][half*2], v1 = acc[fm][fn][half*2+1];
        if (mode == 0){
          *(float2*)&C[(size_t)row*N + col] = make_float2(v0, v1);
        } else if (mode == 1){
          float2 bb = *(const float2*)(bias + col);
          v0 += bb.x; v1 += bb.y;
          v0 = v0 / (1.f + __expf(-v0));
          v1 = v1 / (1.f + __expf(-v1));
          u32 h, l; splt(v0, v1, h, l);
          ((u32*)Ch)[((size_t)row*N + col) >> 1] = h;
          ((u32*)Cl)[((size_t)row*N + col) >> 1] = l;
        } else {
          float2 bb = *(const float2*)(bias + col);
          *(float2*)&C[(size_t)row*N + col] = make_float2(v0 + bb.x, v1 + bb.y);
        }
      }
    }
  }
}

// ---- prep: W[K][N] -> Wt hi/lo [N][K] ----
__global__ void wconv(const float* __restrict__ W, bf16* __restrict__ Wh,
                      bf16* __restrict__ Wl, int K, int N){
  int idx = blockIdx.x*256 + threadIdx.x;
  if (idx >= K*N) return;
  int k = idx / N, nn = idx - k*N;
  float f = W[idx];
  bf16 h = __float2bfloat16_rn(f);
  Wh[(size_t)nn*K + k] = h;
  Wl[(size_t)nn*K + k] = __float2bfloat16_rn(f - __bfloat162float(h));
}
// ---- prep: elementwise fp32 -> bf16 hi/lo (float4 granularity) ----
__global__ void aconv(const float* __restrict__ A, bf16* __restrict__ Ahh,
                      bf16* __restrict__ All, int n4){
  int i = blockIdx.x*256 + threadIdx.x;
  if (i >= n4) return;
  float4 v = ((const float4*)A)[i];
  u32 h0,l0,h1,l1;
  splt(v.x, v.y, h0, l0); splt(v.z, v.w, h1, l1);
  ((uint2*)Ahh)[i] = make_uint2(h0, h1);
  ((uint2*)All)[i] = make_uint2(l0, l1);
}

__global__ void glue1(const float* __restrict__ x, int n){
  int nd = blockIdx.x, j = threadIdx.x;
  const float* vr = g_v + (size_t)nd*1536;
  float a0=vr[j], a1=vr[512+j], a2=vr[1024+j];
  float b0=vr[256+j], b1=vr[768+j], b2=vr[1280+j];
  float xx = x[(size_t)nd*256 + j];
  float sc = sqrtf(a0*a0 + a1*a1 + a2*a2);
  g_dot[(size_t)nd*256 + j] = (a0*b0 + a1*b1 + a2*b2) * 0.0625f;
  size_t o0 = (size_t)nd*512 + j, o1 = o0 + 256;
  bf16 xh = __float2bfloat16_rn(xx);
  bf16 sh = __float2bfloat16_rn(sc);
  g_hch[o0] = xh; g_hcl[o0] = __float2bfloat16_rn(xx - __bfloat162float(xh));
  g_hch[o1] = sh; g_hcl[o1] = __float2bfloat16_rn(sc - __bfloat162float(sh));
}
__global__ void glue2(float* __restrict__ out, int n){
  int nd = blockIdx.x, j = threadIdx.x;
  const float* xv = g_xv + (size_t)nd*768;
  float x1 = xv[j], x2 = xv[256+j], x3 = xv[512+j];
  out[(size_t)nd*256 + j] = (x1 + x2 + g_dot[(size_t)nd*256+j]) * 0.70710678118654752f;
  const float* vr = g_v + (size_t)nd*1536 + 256;
  float* dv = out + (size_t)n*256 + (size_t)nd*768;
  dv[j]     = x3 * vr[j];
  dv[256+j] = x3 * vr[512+j];
  dv[512+j] = x3 * vr[1024+j];
}

extern "C" void kernel_launch(void* const* d_in, const int* in_sizes, int n_in,
                              void* d_out, int out_size)
{
  const float* x   = (const float*)d_in[0];
  const float* vec = (const float*)d_in[1];
  const float* We  = (const float*)d_in[3];
  const float* W1  = (const float*)d_in[4];
  const float* b1  = (const float*)d_in[5];
  const float* W2  = (const float*)d_in[6];
  const float* b2  = (const float*)d_in[7];
  float* out = (float*)d_out;
  const int n = in_sizes[0] / 256;
  const int M1 = 3*n;

  float *pv, *pxv;
  bf16 *pvh,*pvl,*phch,*phcl,*phh,*phl,*pWeh,*pWel,*pW1h,*pW1l,*pW2h,*pW2l;
  cudaGetSymbolAddress((void**)&pv,  g_v);
  cudaGetSymbolAddress((void**)&pxv, g_xv);
  cudaGetSymbolAddress((void**)&pvh, g_vh);  cudaGetSymbolAddress((void**)&pvl, g_vl);
  cudaGetSymbolAddress((void**)&phch,g_hch); cudaGetSymbolAddress((void**)&phcl,g_hcl);
  cudaGetSymbolAddress((void**)&phh, g_hh);  cudaGetSymbolAddress((void**)&phl, g_hl);
  cudaGetSymbolAddress((void**)&pWeh,g_Weh); cudaGetSymbolAddress((void**)&pWel,g_Wel);
  cudaGetSymbolAddress((void**)&pW1h,g_W1h); cudaGetSymbolAddress((void**)&pW1l,g_W1l);
  cudaGetSymbolAddress((void**)&pW2h,g_W2h); cudaGetSymbolAddress((void**)&pW2l,g_W2l);

  cudaFuncSetAttribute(gemm_k, cudaFuncAttributeMaxDynamicSharedMemorySize, SMEM_BYTES);

  wconv<<<(256*512+255)/256, 256>>>(We, pWeh, pWel, 256, 512);
  wconv<<<(512*256+255)/256, 256>>>(W1, pW1h, pW1l, 512, 256);
  wconv<<<(256*768+255)/256, 256>>>(W2, pW2h, pW2l, 256, 768);
  aconv<<<((M1*64)+255)/256, 256>>>(vec, pvh, pvl, M1*64);

  gemm_k<<<dim3(4,(M1+127)/128), 128, SMEM_BYTES>>>(
      pvh, pvl, pWeh, pWel, (const float*)0, pv, (bf16*)0, (bf16*)0, M1, 256, 512, 0);
  glue1<<<n, 256>>>(x, n);
  gemm_k<<<dim3(2,(n+127)/128), 128, SMEM_BYTES>>>(
      phch, phcl, pW1h, pW1l, b1, (float*)0, phh, phl, n, 512, 256, 1);
  gemm_k<<<dim3(6,(n+127)/128), 128, SMEM_BYTES>>>(
      phh, phl, pW2h, pW2l, b2, pxv, (bf16*)0, (bf16*)0, n, 256, 768, 2);
  glue2<<<n, 256>>>(out, n);
}